// round 8
// baseline (speedup 1.0000x reference)
#include <cuda_runtime.h>
#include <cuda_fp16.h>
#include <cstdint>

#define NNETS 76
#define HD    64

__device__ float g_tau[NNETS * 32768];

// gas-channel index table (padded with -1)
__constant__ int IDX[30][6] = {
    { 0,29,42,51,54,63}, { 0,29,42,51,54,63}, { 1,30,43,52,55,64},
    { 2,31,44,53,56,65}, { 3,57,-1,-1,-1,-1}, { 4,58,-1,-1,-1,-1},
    { 5,45,-1,-1,-1,-1}, { 6,46,-1,-1,-1,-1}, { 7,59,-1,-1,-1,-1},
    { 8,60,-1,-1,-1,-1}, { 9,47,-1,-1,-1,-1}, {10,48,-1,-1,-1,-1},
    {11,61,-1,-1,-1,-1}, {12,62,-1,-1,-1,-1}, {13,49,-1,-1,-1,-1},
    {14,50,-1,-1,-1,-1}, {15,66,-1,-1,-1,-1}, {16,67,-1,-1,-1,-1},
    {17,32,68,-1,-1,-1}, {18,33,69,-1,-1,-1}, {19,34,70,-1,-1,-1},
    {20,35,71,-1,-1,-1}, {21,36,72,-1,-1,-1}, {22,37,73,-1,-1,-1},
    {23,-1,-1,-1,-1,-1}, {24,-1,-1,-1,-1,-1}, {25,38,-1,-1,-1,-1},
    {26,39,-1,-1,-1,-1}, {27,40,74,-1,-1,-1}, {28,41,75,-1,-1,-1}
};

// ---------------- helpers ----------------
__device__ __forceinline__ unsigned smem_u32(const void* p) {
    unsigned r;
    asm("{ .reg .u64 t; cvta.to.shared.u64 t, %1; cvt.u32.u64 %0, t; }" : "=r"(r) : "l"(p));
    return r;
}
__device__ __forceinline__ unsigned h2u(__half2 h) {
    return *reinterpret_cast<unsigned*>(&h);
}

#define LDSM4(r0, r1, r2, r3, addr)                                           \
    asm volatile("ldmatrix.sync.aligned.m8n8.x4.shared.b16 {%0,%1,%2,%3}, [%4];" \
                 : "=r"(r0), "=r"(r1), "=r"(r2), "=r"(r3) : "r"(addr))

#define MMA(c, a, b0, b1)                                                     \
    asm volatile("mma.sync.aligned.m16n8k16.row.col.f32.f16.f16.f32 "         \
                 "{%0,%1,%2,%3},{%4,%5,%6,%7},{%8,%9},{%0,%1,%2,%3};"         \
                 : "+f"((c)[0]), "+f"((c)[1]), "+f"((c)[2]), "+f"((c)[3])     \
                 : "r"((a)[0]), "r"((a)[1]), "r"((a)[2]), "r"((a)[3]),        \
                   "r"(b0), "r"(b1))

// ---------------------------------------------------------------------------
// MLP kernel: persistent CTAs over flattened (net, 128-row-tile) job list.
// 128 threads = 4 warps; each warp owns 32 rows. Single-pass fp16 mma.
// B (W2) fragments are hoisted into registers once per net.
// ---------------------------------------------------------------------------
__global__ void __launch_bounds__(128, 3)
mlp_mma_kernel(const float* __restrict__ t_p, const float* __restrict__ comp,
               const float* __restrict__ W1, const float* __restrict__ b1,
               const float* __restrict__ W2, const float* __restrict__ b2,
               const float* __restrict__ W3, const float* __restrict__ b3,
               int B)
{
    __shared__ __align__(128) unsigned char sW2hi[HD * 128];  // [j][k] fp16, swizzled
    __shared__ __align__(8) float sW1a[HD], sW1b[HD], sB1[HD], sB2[HD], sW3[HD];
    __shared__ float sB3;

    const int tid = threadIdx.x;
    const int w   = tid >> 5;
    const int l   = tid & 31;
    const int g   = l >> 2;     // group id (row within 8)
    const int tig = l & 3;      // thread-in-group

    const unsigned w2hi_u = smem_u32(sW2hi);

    const int TPN = B >> 7;                       // tiles per net
    const long long J = (long long)NNETS * TPN;   // total jobs
    const int C  = gridDim.x;
    const int js = (int)((J * blockIdx.x) / C);
    const int je = (int)((J * (blockIdx.x + 1)) / C);

    int curnet = -1;
    const float* cg = nullptr;
    float* taun = nullptr;
    float b3v = 0.f;

    unsigned bfr[16][4];   // W2 fragments: [kb*4+np][reg], net-resident

    #pragma unroll 1
    for (int job = js; job < je; ++job) {
        const int net  = job / TPN;
        const int tile = job - net * TPN;

        if (net != curnet) {
            __syncthreads();   // all warps done with previous net's weights
            const float* W2n = W2 + (size_t)net * HD * HD;   // [k][j]
            for (int i = tid; i < HD * HD; i += 128) {
                int k = i >> 6, j = i & 63;
                unsigned off = (unsigned)(j * 128) + ((((unsigned)(k >> 3)) ^ (j & 7)) << 4)
                             + ((k & 7) << 1);
                *(__half*)(sW2hi + off) = __float2half_rn(W2n[i]);
            }
            const float* W1n = W1 + (size_t)net * 2 * HD;
            if (tid < HD) {
                sW1a[tid] = W1n[tid];
                sW1b[tid] = W1n[HD + tid];
                sB1[tid]  = b1[(size_t)net * HD + tid];
                sB2[tid]  = b2[(size_t)net * HD + tid];
                sW3[tid]  = W3[(size_t)net * HD + tid];
            }
            if (tid == 0) sB3 = b3[net];
            __syncthreads();
            // hoist all B fragments into registers (invariant across tiles)
            #pragma unroll
            for (int kb = 0; kb < 4; ++kb) {
                const unsigned csel = 2 * kb + (l >> 4);
                #pragma unroll
                for (int np = 0; np < 4; ++np) {
                    const unsigned n16 = 16 * np + (((unsigned)(l >> 3) & 1) << 3) + (l & 7);
                    const unsigned off = n16 * 128 + ((csel ^ (n16 & 7)) << 4);
                    LDSM4(bfr[kb * 4 + np][0], bfr[kb * 4 + np][1],
                          bfr[kb * 4 + np][2], bfr[kb * 4 + np][3], w2hi_u + off);
                }
            }
            curnet = net;
            const int gi = (net < 29) ? 0 : (net < 42) ? 1 : (net < 51) ? 2
                         : (net < 54) ? 3 : (net < 63) ? 4 : 5;
            cg   = comp + (size_t)gi * B;
            taun = g_tau + (size_t)net * B;
            b3v  = sB3;
        }

        const int tbase = tile * 128;
        const int rloc0 = 32 * w + g;   // local rows: rloc0, +8, +16, +24

        // t_p for my 4 fragment rows
        float2 tp[4];
        #pragma unroll
        for (int i = 0; i < 4; ++i)
            tp[i] = ((const float2*)t_p)[tbase + rloc0 + 8 * i];

        // accumulators init with b2
        float acc[2][8][4];
        #pragma unroll
        for (int nb = 0; nb < 8; ++nb) {
            float2 b2v = *(const float2*)&sB2[8 * nb + 2 * tig];
            #pragma unroll
            for (int mb = 0; mb < 2; ++mb) {
                acc[mb][nb][0] = b2v.x; acc[mb][nb][1] = b2v.y;
                acc[mb][nb][2] = b2v.x; acc[mb][nb][3] = b2v.y;
            }
        }

        #pragma unroll
        for (int kb = 0; kb < 4; ++kb) {
            // ---- layer 1: my A-fragment elements for this k-block ----
            const int k0 = 16 * kb + 2 * tig;        // and k0+8
            const float2 wa0 = *(const float2*)&sW1a[k0];
            const float2 wa1 = *(const float2*)&sW1a[k0 + 8];
            const float2 wb0 = *(const float2*)&sW1b[k0];
            const float2 wb1 = *(const float2*)&sW1b[k0 + 8];
            const float2 bb0 = *(const float2*)&sB1[k0];
            const float2 bb1 = *(const float2*)&sB1[k0 + 8];

            unsigned Ahi[2][4];
            #pragma unroll
            for (int i = 0; i < 4; ++i) {
                const float tx = tp[i].x, ty = tp[i].y;
                float h00 = fmaxf(fmaf(tx, wa0.x, fmaf(ty, wb0.x, bb0.x)), 0.f);
                float h01 = fmaxf(fmaf(tx, wa0.y, fmaf(ty, wb0.y, bb0.y)), 0.f);
                float h10 = fmaxf(fmaf(tx, wa1.x, fmaf(ty, wb1.x, bb1.x)), 0.f);
                float h11 = fmaxf(fmaf(tx, wa1.y, fmaf(ty, wb1.y, bb1.y)), 0.f);
                __half2 hh0 = __floats2half2_rn(h00, h01);
                __half2 hh1 = __floats2half2_rn(h10, h11);
                const int mb = i >> 1, sl = i & 1;
                Ahi[mb][sl]     = h2u(hh0);
                Ahi[mb][2 + sl] = h2u(hh1);
            }

            // ---- mma from register-resident B fragments ----
            #pragma unroll
            for (int np = 0; np < 4; ++np) {
                const unsigned* bh = bfr[kb * 4 + np];
                #pragma unroll
                for (int mb = 0; mb < 2; ++mb) {
                    MMA(acc[mb][2 * np],     Ahi[mb], bh[0], bh[2]);
                    MMA(acc[mb][2 * np + 1], Ahi[mb], bh[1], bh[3]);
                }
            }
        }

        // ---- epilogue: relu, W3 dot, quad reduce, tau store ----
        #pragma unroll
        for (int mb = 0; mb < 2; ++mb) {
            float p0 = 0.f, p1 = 0.f;
            #pragma unroll
            for (int nb = 0; nb < 8; ++nb) {
                float2 w3v = *(const float2*)&sW3[8 * nb + 2 * tig];
                p0 = fmaf(fmaxf(acc[mb][nb][0], 0.f), w3v.x, p0);
                p0 = fmaf(fmaxf(acc[mb][nb][1], 0.f), w3v.y, p0);
                p1 = fmaf(fmaxf(acc[mb][nb][2], 0.f), w3v.x, p1);
                p1 = fmaf(fmaxf(acc[mb][nb][3], 0.f), w3v.y, p1);
            }
            p0 += __shfl_xor_sync(0xffffffffu, p0, 1);
            p0 += __shfl_xor_sync(0xffffffffu, p0, 2);
            p1 += __shfl_xor_sync(0xffffffffu, p1, 1);
            p1 += __shfl_xor_sync(0xffffffffu, p1, 2);
            if (tig == 0) {
                const int r0 = tbase + 32 * w + 16 * mb + g;
                const int r1 = r0 + 8;
                taun[r0] = fmaxf(p0 + b3v, 0.f) * cg[r0];
                taun[r1] = fmaxf(p1 + b3v, 0.f) * cg[r1];
            }
        }
    }
}

// ---------------------------------------------------------------------------
// Kernel B: (section, b-chunk) parallel combine. 90 sections x (B/256) chunks.
// ---------------------------------------------------------------------------
__global__ void __launch_bounds__(256)
combine_kernel(const float* __restrict__ comp,
               const float* __restrict__ null_lw, const float* __restrict__ null_iw,
               const float* __restrict__ W_lw, const float* __restrict__ b_lw,
               const float* __restrict__ W_iw, const float* __restrict__ b_iw,
               float* __restrict__ out, int B)
{
    const int chunks = B >> 8;
    const int s  = blockIdx.x / chunks;             // 0..89
    const int b  = (blockIdx.x - s * chunks) * 256 + threadIdx.x;

    if (s < 30) {
        float sum = 0.f;
        #pragma unroll
        for (int i = 0; i < 6; ++i) {
            const int n = IDX[s][i];
            if (n >= 0) sum += g_tau[(size_t)n * B + b];
        }
        out[(size_t)s * B + b] = sum;
    } else if (s < 60) {
        const int c = s - 30;
        out[(size_t)s * B + b] =
            fmaxf(fmaf(null_lw[b], W_lw[c], b_lw[c]), 0.f) * comp[(size_t)6 * B + b];
    } else {
        const int c = s - 60;
        out[(size_t)s * B + b] =
            fmaxf(fmaf(null_iw[b], W_iw[c], b_iw[c]), 0.f) * comp[(size_t)7 * B + b];
    }
}

// ---------------------------------------------------------------------------
extern "C" void kernel_launch(void* const* d_in, const int* in_sizes, int n_in,
                              void* d_out, int out_size)
{
    const float* t_p     = (const float*)d_in[0];
    const float* comp    = (const float*)d_in[1];
    const float* null_lw = (const float*)d_in[2];
    const float* null_iw = (const float*)d_in[3];
    const float* W1      = (const float*)d_in[4];
    const float* b1      = (const float*)d_in[5];
    const float* W2      = (const float*)d_in[6];
    const float* b2      = (const float*)d_in[7];
    const float* W3      = (const float*)d_in[8];
    const float* b3      = (const float*)d_in[9];
    const float* W_lw    = (const float*)d_in[10];
    const float* b_lw    = (const float*)d_in[11];
    const float* W_iw    = (const float*)d_in[12];
    const float* b_iw    = (const float*)d_in[13];

    const int B = in_sizes[0] / 2;   // t_p is [B, 2]

    mlp_mma_kernel<<<444, 128>>>(t_p, comp, W1, b1, W2, b2, W3, b3, B);

    combine_kernel<<<90 * (B >> 8), 256>>>(comp, null_lw, null_iw,
                                           W_lw, b_lw, W_iw, b_iw,
                                           (float*)d_out, B);
}